// round 17
// baseline (speedup 1.0000x reference)
#include <cuda_runtime.h>
#include <cuda_fp16.h>
#include <stdint.h>
#include <math_constants.h>

#define K_CODES 8192
#define DIM     256
#define NTOK    32768
#define HW      1024

#define OUT_LOSS 0
#define OUT_Q    1
#define OUT_IDX  (OUT_Q  + 32*DIM*HW)
#define OUT_CNT  (OUT_IDX + NTOK)
#define OUT_W    (OUT_CNT + K_CODES)
#define OUT_CB   (OUT_W   + K_CODES*DIM)

#define WINDOW 3.0e-4f
#define NTILE  (K_CODES / 128)   // 64
#define CAP    6

// ---------------- device scratch ----------------
__device__ __align__(128) __half g_x16T[NTOK * DIM];     // half(x), [token][d]
__device__ __align__(128) __half g_cb16[K_CODES * DIM];  // half(cb * 2^13), [code][d]
__device__ __align__(128) float  g_tmin[NTILE * NTOK];   // [tile][token] tile minima
__device__ __align__(128) int2   g_cand[(size_t)NTILE * NTOK * CAP];
__device__ __align__(128) int    g_ccnt[(size_t)NTILE * NTOK];
__device__ float  g_cbnorm[K_CODES];
__device__ float  g_znorm[NTOK];
__device__ double g_zpart[16][NTOK];
__device__ float  g_counts[K_CODES];
__device__ float  g_dw[K_CODES * DIM];
__device__ double g_loss;
__device__ int    g_idx[NTOK];

__device__ __forceinline__ uint32_t smem_u32(const void* p) {
    uint32_t a;
    asm("{ .reg .u64 t; cvta.to.shared.u64 t, %1; cvt.u32.u64 %0, t; }" : "=r"(a) : "l"(p));
    return a;
}
#define CP16(dst, src) \
    asm volatile("cp.async.ca.shared.global [%0], [%1], 16;" :: "r"(dst), "l"(src))
#define CP_COMMIT() asm volatile("cp.async.commit_group;" ::: "memory")
#define CP_WAIT0()  asm volatile("cp.async.wait_group 0;" ::: "memory")

#define MMA_F16(c, a, b) \
    asm volatile("mma.sync.aligned.m16n8k16.row.col.f32.f16.f16.f32 " \
        "{%0,%1,%2,%3}, {%4,%5,%6,%7}, {%8,%9}, {%0,%1,%2,%3};" \
        : "+f"((c)[0]), "+f"((c)[1]), "+f"((c)[2]), "+f"((c)[3]) \
        : "r"((a)[0]), "r"((a)[1]), "r"((a)[2]), "r"((a)[3]), "r"((b)[0]), "r"((b)[1]))

// ---------------- init ----------------
__global__ void init_kernel() {
    int i = blockIdx.x * blockDim.x + threadIdx.x;
    if (i < K_CODES * DIM) g_dw[i] = 0.0f;
    if (i < K_CODES)       g_counts[i] = 0.0f;
    if (i == 0)            g_loss = 0.0;
}

// ---------------- x -> half, transposed to [token][d] (R14-exact) ----------------
__global__ void decomp_x16T(const float* __restrict__ x) {
    __shared__ float tile[32][33];
    int tx = threadIdx.x, ty = threadIdx.y;
    int hw0 = blockIdx.x * 32, d0 = blockIdx.y * 32, b = blockIdx.z;
    tile[ty][tx] = x[(size_t)b * DIM * HW + (size_t)(d0 + ty) * HW + hw0 + tx];
    __syncthreads();
    g_x16T[(size_t)(b * 1024 + hw0 + ty) * DIM + d0 + tx] = __float2half_rn(tile[tx][ty]);
}

// ---------------- cb -> half(cb * 2^13) (R14-exact) ----------------
__global__ void decomp_cb16(const float* __restrict__ cb) {
    int i = blockIdx.x * blockDim.x + threadIdx.x;
    g_cb16[i] = __float2half_rn(cb[i] * 8192.0f);
}

// ---------------- token norm partials (fp64), 16 chunks of 16 d's (R14-exact) ----
__global__ void znorm_part(const float* __restrict__ x) {
    int t4 = blockIdx.x * blockDim.x + threadIdx.x;
    int chunk = blockIdx.y;
    int b   = t4 >> 8;
    int hw4 = t4 & 255;
    const float4* p = (const float4*)(x + (size_t)b * DIM * HW
                                      + (size_t)(chunk * 16) * HW) + hw4;
    double s0 = 0.0, s1 = 0.0, s2 = 0.0, s3 = 0.0;
    #pragma unroll
    for (int d = 0; d < 16; d++) {
        float4 v = p[(size_t)d * 256];
        double vx = (double)v.x, vy = (double)v.y, vz = (double)v.z, vw = (double)v.w;
        s0 = fma(vx, vx, s0);
        s1 = fma(vy, vy, s1);
        s2 = fma(vz, vz, s2);
        s3 = fma(vw, vw, s3);
    }
    int token = (b << 10) + hw4 * 4;
    g_zpart[chunk][token + 0] = s0;
    g_zpart[chunk][token + 1] = s1;
    g_zpart[chunk][token + 2] = s2;
    g_zpart[chunk][token + 3] = s3;
}
__global__ void znorm_comb() {
    int token = blockIdx.x * blockDim.x + threadIdx.x;
    double a0 = (g_zpart[0][token]  + g_zpart[1][token])
              + (g_zpart[2][token]  + g_zpart[3][token]);
    double a1 = (g_zpart[4][token]  + g_zpart[5][token])
              + (g_zpart[6][token]  + g_zpart[7][token]);
    double a2 = (g_zpart[8][token]  + g_zpart[9][token])
              + (g_zpart[10][token] + g_zpart[11][token]);
    double a3 = (g_zpart[12][token] + g_zpart[13][token])
              + (g_zpart[14][token] + g_zpart[15][token]);
    g_znorm[token] = (float)((a0 + a1) + (a2 + a3));
}

// ---------------- codebook norms (fp64 -> fp32) (R14-exact) ----------------
__global__ void cbnorm_kernel(const float* __restrict__ cb) {
    int gt = blockIdx.x * blockDim.x + threadIdx.x;
    int code = gt >> 5, lane = gt & 31;
    if (code >= K_CODES) return;
    const float* r = cb + (size_t)code * DIM;
    double s = 0.0;
    #pragma unroll
    for (int i = lane; i < DIM; i += 32) {
        double v = (double)__ldg(r + i);
        s = fma(v, v, s);
    }
    #pragma unroll
    for (int o = 16; o; o >>= 1) s += __shfl_down_sync(0xFFFFFFFFu, s, o);
    if (lane == 0) g_cbnorm[code] = (float)s;
}

// ---------------- fp16 screening GEMM + tile minima + candidate lists ----------
// Mainloop identical to R14; epilogue stages fp32 d, emits tmin + <=CAP candidates
// per (tile, token) with threshold tmin + W. No d_hh materialization.
#define AP      40
#define TILE_H  (128 * AP)
#define STAGE_H (2 * TILE_H)          // 20480 B per stage
#define NKSTEP  8
#define EPI_PF  132                   // epilogue pitch (floats)
#define SMEM_B  (128 * EPI_PF * 4)    // 67584 B >= pipeline's 40960 B

__global__ void __launch_bounds__(256, 2)
screen_gemm16(void) {
    extern __shared__ __half smh[];
    float* smf = (float*)smh;
    const uint32_t smb = smem_u32(smh);

    const int tid  = threadIdx.x;
    const int lane = tid & 31;
    const int wid  = tid >> 5;
    const int g    = lane >> 2;
    const int q    = lane & 3;

    const int tb  = blockIdx.y;
    const int ct  = blockIdx.x;
    const int nt0 = ct * 128;

    const int mbase = (wid & 3) * 32;
    const int nbase = (wid >> 2) * 64;

    float acc[2][8][4];
    #pragma unroll
    for (int mf = 0; mf < 2; mf++)
        #pragma unroll
        for (int nf = 0; nf < 8; nf++)
            #pragma unroll
            for (int c = 0; c < 4; c++) acc[mf][nf][c] = 0.0f;

    auto issue = [&](int s, int k0) {
        const __half* ap = g_x16T + (size_t)(tb * 128) * DIM + k0;
        const __half* bp = g_cb16 + (size_t)nt0 * DIM + k0;
        #pragma unroll
        for (int i = 0; i < 2; i++) {
            int idx = i * 256 + tid;
            int row = idx >> 2;
            int seg = idx & 3;
            CP16(smb + 2u * (s * STAGE_H + row * AP + seg * 8),
                 ap + (size_t)row * DIM + seg * 8);
            CP16(smb + 2u * (s * STAGE_H + TILE_H + row * AP + seg * 8),
                 bp + (size_t)row * DIM + seg * 8);
        }
        CP_COMMIT();
    };

    issue(0, 0);

    #pragma unroll 1
    for (int ks = 0; ks < NKSTEP; ks++) {
        CP_WAIT0();
        __syncthreads();
        if (ks < NKSTEP - 1) issue((ks + 1) & 1, (ks + 1) * 32);

        const uint32_t* A32 = (const uint32_t*)(smh + (ks & 1) * STAGE_H);
        const uint32_t* B32 = A32 + TILE_H / 2;

        #pragma unroll
        for (int kl2 = 0; kl2 < 2; kl2++) {
            const int klh = kl2 * 8;
            uint32_t af[2][4], bf[8][2];
            #pragma unroll
            for (int mf = 0; mf < 2; mf++) {
                int m = mbase + mf * 16 + g;
                af[mf][0] = A32[m * (AP / 2) + klh + q];
                af[mf][1] = A32[(m + 8) * (AP / 2) + klh + q];
                af[mf][2] = A32[m * (AP / 2) + klh + 4 + q];
                af[mf][3] = A32[(m + 8) * (AP / 2) + klh + 4 + q];
            }
            #pragma unroll
            for (int nf = 0; nf < 8; nf++) {
                int n = nbase + nf * 8 + g;
                bf[nf][0] = B32[n * (AP / 2) + klh + q];
                bf[nf][1] = B32[n * (AP / 2) + klh + 4 + q];
            }
            #pragma unroll
            for (int mf = 0; mf < 2; mf++)
                #pragma unroll
                for (int nf = 0; nf < 8; nf++)
                    MMA_F16(acc[mf][nf], af[mf], bf[nf]);
        }
    }

    // epilogue: stage fp32 d = fmaf(-2^-12, dot_scaled, cn) in smem
    __syncthreads();
    #pragma unroll
    for (int mf = 0; mf < 2; mf++)
        #pragma unroll
        for (int h = 0; h < 2; h++) {
            int m = mbase + mf * 16 + g + h * 8;
            #pragma unroll
            for (int nf = 0; nf < 8; nf++) {
                int n = nbase + nf * 8 + q * 2;
                float d0 = fmaf(-0.000244140625f, acc[mf][nf][h * 2 + 0],
                                __ldg(&g_cbnorm[nt0 + n]));
                float d1 = fmaf(-0.000244140625f, acc[mf][nf][h * 2 + 1],
                                __ldg(&g_cbnorm[nt0 + n + 1]));
                *(float2*)&smf[m * EPI_PF + n] = make_float2(d0, d1);
            }
        }
    __syncthreads();

    // per-token: tile min + candidate list (d <= tmin + W), count always stored
    if (tid < 128) {
        const float* rp = &smf[tid * EPI_PF];
        float mn = CUDART_INF_F;
        #pragma unroll
        for (int i = 0; i < 32; i++) {
            float4 v = ((const float4*)rp)[i];
            mn = fminf(mn, fminf(fminf(v.x, v.y), fminf(v.z, v.w)));
        }
        int token = tb * 128 + tid;
        size_t pc = (size_t)ct * NTOK + token;
        g_tmin[pc] = mn;
        float thr = mn + WINDOW;
        int cnt = 0;
        #pragma unroll 4
        for (int i = 0; i < 128; i++) {
            float d = rp[i];
            if (d <= thr) {
                if (cnt < CAP)
                    g_cand[pc * CAP + cnt] = make_int2(nt0 + i, __float_as_int(d));
                cnt++;
            }
        }
        g_ccnt[pc] = cnt;
    }
}

// ---------------- scan (tile-min pruned, candidate lists) + rescore ----------
#define MAXCAND 1024
__global__ void __launch_bounds__(256, 4)
scan_rescore(const float* __restrict__ x, const float* __restrict__ cb,
             float* __restrict__ out) {
    __shared__ float stmin[NTILE];
    __shared__ int   sqtiles[NTILE];
    __shared__ int   sqcnt;
    __shared__ float sthr;
    __shared__ int   scnt;
    __shared__ int   scand[MAXCAND];
    __shared__ unsigned long long sbest;

    const int t = blockIdx.x;
    const int tid = threadIdx.x, lane = tid & 31, wid = tid >> 5;

    if (tid < NTILE) stmin[tid] = g_tmin[(size_t)tid * NTOK + t];
    if (tid == 0) { sqcnt = 0; scnt = 0; sbest = 0xFFFFFFFFFFFFFFFFull; }
    __syncthreads();

    if (wid == 0) {
        float mm = fminf(stmin[lane], stmin[lane + 32]);
        #pragma unroll
        for (int o = 16; o; o >>= 1) mm = fminf(mm, __shfl_down_sync(0xFFFFFFFFu, mm, o));
        if (lane == 0) sthr = mm + WINDOW;
    }
    __syncthreads();
    const float thr = sthr;

    if (tid < NTILE && stmin[tid] <= thr) {
        int p = atomicAdd(&sqcnt, 1);
        sqtiles[p] = tid;
    }
    __syncthreads();

    // phase 2: qualifying tiles -> stored candidates, or full tile on overflow
    for (int qi = wid; qi < sqcnt; qi += 8) {
        int ct = sqtiles[qi];
        size_t pc = (size_t)ct * NTOK + t;
        int cnt = g_ccnt[pc];
        if (cnt <= CAP) {
            if (lane < cnt) {
                int2 e = g_cand[pc * CAP + lane];
                if (__int_as_float(e.y) <= thr) {
                    int p = atomicAdd(&scnt, 1);
                    if (p < MAXCAND) scand[p] = e.x;
                }
            }
        } else {
            #pragma unroll
            for (int i = 0; i < 4; i++) {
                int p = atomicAdd(&scnt, 1);
                if (p < MAXCAND) scand[p] = ct * 128 + lane + i * 32;
            }
        }
    }
    __syncthreads();
    int ncand = min(scnt, MAXCAND);

    const int b = t >> 10, hw = t & 1023;
    const float* xbase = x + (size_t)b * DIM * HW + hw;
    const float zn = g_znorm[t];

    for (int j = wid; j < ncand; j += 8) {
        int c = scand[j];
        const float* crow = cb + (size_t)c * DIM;
        double s = 0.0;
        #pragma unroll
        for (int i = 0; i < 8; i++) {
            int d = lane + i * 32;
            double xv = (double)__ldg(xbase + (size_t)d * HW);
            double cv = (double)__ldg(crow + d);
            s = fma(xv, cv, s);
        }
        #pragma unroll
        for (int o = 16; o; o >>= 1) s += __shfl_down_sync(0xFFFFFFFFu, s, o);
        if (lane == 0) {
            float dotf = (float)s;
            float t1 = __fadd_rn(zn, __ldg(&g_cbnorm[c]));
            float d  = __fsub_rn(t1, __fmul_rn(2.0f, dotf));
            unsigned int e = __float_as_uint(d);
            e = (e & 0x80000000u) ? ~e : (e | 0x80000000u);
            atomicMin(&sbest, ((unsigned long long)e << 32) | (unsigned int)c);
        }
    }
    __syncthreads();
    if (tid == 0) {
        int id = (int)(sbest & 0xFFFFFFFFull);
        g_idx[t] = id;
        out[OUT_IDX + t] = (float)id;
        atomicAdd(&g_counts[id], 1.0f);
    }
}

// ---------------- quantized output + loss + dw (fused, coalesced) ----------------
__global__ void quant_loss_dw(const float* __restrict__ x,
                              const float* __restrict__ cb,
                              float* __restrict__ out) {
    int c = blockIdx.x, b = blockIdx.y;
    int tid = threadIdx.x, lane = tid & 31;
    float ls = 0.0f;
    #pragma unroll
    for (int it = 0; it < 4; it++) {
        int hw = it * 256 + tid;
        int n  = (b << 10) + hw;
        int id = g_idx[n];
        float qv = __ldg(cb + (size_t)id * DIM + c);
        size_t off = (size_t)b * DIM * HW + (size_t)c * HW + hw;
        float xv = x[off];
        out[OUT_Q + off] = __fadd_rn(xv, __fsub_rn(qv, xv));
        float d = __fsub_rn(qv, xv);
        ls = fmaf(d, d, ls);
        atomicAdd(&g_dw[(size_t)id * DIM + c], xv);
    }
    double ds = (double)ls;
    #pragma unroll
    for (int o = 16; o; o >>= 1) ds += __shfl_down_sync(0xFFFFFFFFu, ds, o);
    if (lane == 0) atomicAdd(&g_loss, ds);
}

// ---------------- EMA finalize ----------------
__global__ void final_kernel(const float* __restrict__ ema_count,
                             const float* __restrict__ ema_weight,
                             float* __restrict__ out) {
    int k = blockIdx.x;
    int c = threadIdx.x;
    float nc = ema_count[k] * 0.95f + 0.05f * g_counts[k];
    const float denom = (float)(32768.0 + 8192.0 * 1e-5);
    nc = (nc + 1e-5f) / denom * 32768.0f;
    float w = ema_weight[(size_t)k * DIM + c] * 0.95f + 0.05f * g_dw[(size_t)k * DIM + c];
    out[OUT_W  + (size_t)k * DIM + c] = w;
    out[OUT_CB + (size_t)k * DIM + c] = w / nc;
    if (c == 0) out[OUT_CNT + k] = nc;
    if (k == 0 && c == 0) {
        double mean = g_loss / (double)((size_t)NTOK * DIM);
        out[OUT_LOSS] = 0.25f * (float)mean;
    }
}

extern "C" void kernel_launch(void* const* d_in, const int* in_sizes, int n_in,
                              void* d_out, int out_size) {
    const float* x          = (const float*)d_in[0];
    const float* cb         = (const float*)d_in[1];
    const float* ema_count  = (const float*)d_in[2];
    const float* ema_weight = (const float*)d_in[3];
    float* out = (float*)d_out;

    static int smem_set = 0;
    if (!smem_set) {
        cudaFuncSetAttribute(screen_gemm16,
                             cudaFuncAttributeMaxDynamicSharedMemorySize, SMEM_B);
        smem_set = 1;
    }

    init_kernel<<<(K_CODES * DIM + 255) / 256, 256>>>();
    decomp_x16T<<<dim3(HW / 32, DIM / 32, 32), dim3(32, 32)>>>(x);
    decomp_cb16<<<K_CODES * DIM / 256, 256>>>(cb);
    znorm_part<<<dim3(NTOK / 4 / 256, 16), 256>>>(x);
    znorm_comb<<<NTOK / 256, 256>>>();
    cbnorm_kernel<<<(K_CODES * 32 + 255) / 256, 256>>>(cb);
    screen_gemm16<<<dim3(K_CODES / 128, NTOK / 128), 256, SMEM_B>>>();
    scan_rescore<<<NTOK, 256>>>(x, cb, out);
    quant_loss_dw<<<dim3(DIM, 32), 256>>>(x, cb, out);
    final_kernel<<<K_CODES, DIM>>>(ema_count, ema_weight, out);
}